// round 4
// baseline (speedup 1.0000x reference)
#include <cuda_runtime.h>
#include <math.h>

// Problem constants (shapes fixed by the dataset)
#define D_DIM   256
#define E_DIM   256
#define K_NEIGH 32
#define TBR     32          // B-rows per block
#define THREADS 256

// Scratch (no allocations allowed): fused weight [512][256] and fused bias [256]
__device__ float g_Wz[512 * 256];
__device__ float g_bc[256];

// ---------------------------------------------------------------------------
// Prep kernel: build g_Wz and g_bc.
//   rows 0..255   : Wc[d][e]  = sum_j W_init[d][j] * W_final[j][e]
//   rows 256..511 : copy of W_final[256..511][e]
//   block 512     : bc[e] = b_final[e] + sum_j b_init[j] * W_final[j][e]
// ---------------------------------------------------------------------------
__global__ void __launch_bounds__(256) prep_kernel(const float* __restrict__ W_init,
                                                   const float* __restrict__ b_init,
                                                   const float* __restrict__ W_final,
                                                   const float* __restrict__ b_final) {
    __shared__ float sh[256];
    const int d = blockIdx.x;
    const int e = threadIdx.x;

    if (d < 256) {
        sh[e] = W_init[d * 256 + e];
        __syncthreads();
        float s = 0.f;
#pragma unroll 8
        for (int j = 0; j < 256; j++)
            s += sh[j] * W_final[j * 256 + e];
        g_Wz[d * 256 + e] = s;
    } else if (d < 512) {
        g_Wz[d * 256 + e] = W_final[d * 256 + e];
    } else {
        sh[e] = b_init[e];
        __syncthreads();
        float s = b_final[e];
#pragma unroll 8
        for (int j = 0; j < 256; j++)
            s += sh[j] * W_final[j * 256 + e];
        g_bc[e] = s;
    }
}

// ---------------------------------------------------------------------------
// Fused kernel: gather + weighted-mean aggregate + GEMM(512->256) + swish.
// Block: 256 threads, TBR=32 rows of B.
// smem: A tile [32][512] (self feats | neigh aggregate) + W stage [8][256]
// ---------------------------------------------------------------------------
__global__ void __launch_bounds__(THREADS) fused_kernel(const int*   __restrict__ nodes,
                                                        const int*   __restrict__ neigh_idx,
                                                        const float* __restrict__ neigh_w,
                                                        const float* __restrict__ features,
                                                        float*       __restrict__ out,
                                                        int B) {
    extern __shared__ float smem[];
    float* sA = smem;                 // 32 * 512
    float* sW = smem + TBR * 512;     // 8 * 256

    const int tid  = threadIdx.x;
    const int wid  = tid >> 5;
    const int lane = tid & 31;
    const int b0   = blockIdx.x * TBR;

    // ---------------- Phase 1: build activation tile ----------------
    // Warp `wid` owns rows wid*4 .. wid*4+3.
#pragma unroll
    for (int r = 0; r < 4; r++) {
        const int i = wid * 4 + r;
        const int b = b0 + i;
        float* dst = sA + i * 512;

        if (b < B) {
            // self features
            const int node = nodes[b];
            const float4* fs = (const float4*)(features + (size_t)node * D_DIM);
            float4 s0 = fs[lane];
            float4 s1 = fs[lane + 32];
            ((float4*)dst)[lane]      = s0;
            ((float4*)dst)[lane + 32] = s1;

            // neighbor weighted mean
            const float w_mine   = neigh_w[b * K_NEIGH + lane];
            const int   idx_mine = neigh_idx[b * K_NEIGH + lane];
            float ws = w_mine;
#pragma unroll
            for (int o = 16; o > 0; o >>= 1)
                ws += __shfl_xor_sync(0xffffffffu, ws, o);
            const float inv = 1.0f / ws;

            float4 a0 = make_float4(0.f, 0.f, 0.f, 0.f);
            float4 a1 = make_float4(0.f, 0.f, 0.f, 0.f);
#pragma unroll 4
            for (int k = 0; k < K_NEIGH; k++) {
                const float wk = __shfl_sync(0xffffffffu, w_mine, k) * inv;
                const int   ik = __shfl_sync(0xffffffffu, idx_mine, k);
                const float4* fn = (const float4*)(features + (size_t)ik * D_DIM);
                float4 v0 = fn[lane];
                float4 v1 = fn[lane + 32];
                a0.x += wk * v0.x; a0.y += wk * v0.y; a0.z += wk * v0.z; a0.w += wk * v0.w;
                a1.x += wk * v1.x; a1.y += wk * v1.y; a1.z += wk * v1.z; a1.w += wk * v1.w;
            }
            ((float4*)(dst + 256))[lane]      = a0;
            ((float4*)(dst + 256))[lane + 32] = a1;
        } else {
            const float4 z = make_float4(0.f, 0.f, 0.f, 0.f);
            ((float4*)dst)[lane]            = z;
            ((float4*)dst)[lane + 32]       = z;
            ((float4*)(dst + 256))[lane]    = z;
            ((float4*)(dst + 256))[lane + 32] = z;
        }
    }
    __syncthreads();

    // ---------------- Phase 2: GEMM [32][512] x [512][256] ----------------
    // Thread layout: wid -> 4 M-rows (m0 = wid*4); lane -> 8 N-cols split as
    // cols [4*lane .. 4*lane+3] and [128 + 4*lane .. 128 + 4*lane+3]
    // (conflict-free float4 smem reads; broadcast A reads).
    const int m0 = wid * 4;

    float4 acc[4][2];
#pragma unroll
    for (int i = 0; i < 4; i++) {
        acc[i][0] = make_float4(0.f, 0.f, 0.f, 0.f);
        acc[i][1] = make_float4(0.f, 0.f, 0.f, 0.f);
    }

    for (int kk = 0; kk < 512; kk += 8) {
        // stage Wz[kk..kk+7][0..255] into smem (coalesced)
        {
            const int r = wid;  // 8 warps -> 8 rows
            const float4* src = (const float4*)(g_Wz + (size_t)(kk + r) * 256);
            float4 w0 = src[lane];
            float4 w1 = src[lane + 32];
            float4* d = (float4*)(sW + r * 256);
            d[lane]      = w0;
            d[lane + 32] = w1;
        }
        __syncthreads();

#pragma unroll
        for (int p = 0; p < 8; p++) {
            const float a0 = sA[(m0 + 0) * 512 + kk + p];
            const float a1 = sA[(m0 + 1) * 512 + kk + p];
            const float a2 = sA[(m0 + 2) * 512 + kk + p];
            const float a3 = sA[(m0 + 3) * 512 + kk + p];
            const float4 w0 = ((const float4*)(sW + p * 256))[lane];
            const float4 w1 = ((const float4*)(sW + p * 256))[lane + 32];

            acc[0][0].x += a0 * w0.x; acc[0][0].y += a0 * w0.y; acc[0][0].z += a0 * w0.z; acc[0][0].w += a0 * w0.w;
            acc[0][1].x += a0 * w1.x; acc[0][1].y += a0 * w1.y; acc[0][1].z += a0 * w1.z; acc[0][1].w += a0 * w1.w;
            acc[1][0].x += a1 * w0.x; acc[1][0].y += a1 * w0.y; acc[1][0].z += a1 * w0.z; acc[1][0].w += a1 * w0.w;
            acc[1][1].x += a1 * w1.x; acc[1][1].y += a1 * w1.y; acc[1][1].z += a1 * w1.z; acc[1][1].w += a1 * w1.w;
            acc[2][0].x += a2 * w0.x; acc[2][0].y += a2 * w0.y; acc[2][0].z += a2 * w0.z; acc[2][0].w += a2 * w0.w;
            acc[2][1].x += a2 * w1.x; acc[2][1].y += a2 * w1.y; acc[2][1].z += a2 * w1.z; acc[2][1].w += a2 * w1.w;
            acc[3][0].x += a3 * w0.x; acc[3][0].y += a3 * w0.y; acc[3][0].z += a3 * w0.z; acc[3][0].w += a3 * w0.w;
            acc[3][1].x += a3 * w1.x; acc[3][1].y += a3 * w1.y; acc[3][1].z += a3 * w1.z; acc[3][1].w += a3 * w1.w;
        }
        __syncthreads();
    }

    // ---------------- Epilogue: +bias, swish, store ----------------
    const float4 bc0 = ((const float4*)g_bc)[lane];
    const float4 bc1 = ((const float4*)g_bc)[lane + 32];

#pragma unroll
    for (int i = 0; i < 4; i++) {
        const int b = b0 + m0 + i;
        if (b >= B) continue;
        float4 z0 = acc[i][0];
        float4 z1 = acc[i][1];
        z0.x += bc0.x; z0.y += bc0.y; z0.z += bc0.z; z0.w += bc0.w;
        z1.x += bc1.x; z1.y += bc1.y; z1.z += bc1.z; z1.w += bc1.w;

        float4 o0, o1;
        o0.x = z0.x / (1.f + expf(-z0.x));
        o0.y = z0.y / (1.f + expf(-z0.y));
        o0.z = z0.z / (1.f + expf(-z0.z));
        o0.w = z0.w / (1.f + expf(-z0.w));
        o1.x = z1.x / (1.f + expf(-z1.x));
        o1.y = z1.y / (1.f + expf(-z1.y));
        o1.z = z1.z / (1.f + expf(-z1.z));
        o1.w = z1.w / (1.f + expf(-z1.w));

        float* orow = out + (size_t)b * E_DIM;
        ((float4*)orow)[lane]      = o0;
        ((float4*)orow)[lane + 32] = o1;
    }
}

// ---------------------------------------------------------------------------
extern "C" void kernel_launch(void* const* d_in, const int* in_sizes, int n_in,
                              void* d_out, int out_size) {
    const int*   nodes     = (const int*)  d_in[0];
    const int*   neigh_idx = (const int*)  d_in[1];
    const float* neigh_w   = (const float*)d_in[2];
    const float* features  = (const float*)d_in[3];
    const float* W_init    = (const float*)d_in[4];
    const float* b_init    = (const float*)d_in[5];
    const float* W_final   = (const float*)d_in[6];
    const float* b_final   = (const float*)d_in[7];
    float*       out       = (float*)d_out;

    const int B = in_sizes[0];

    prep_kernel<<<513, 256>>>(W_init, b_init, W_final, b_final);

    const int smem_bytes = (TBR * 512 + 8 * 256) * (int)sizeof(float);  // 73728
    static bool attr_set = false;
    if (!attr_set) {
        cudaFuncSetAttribute(fused_kernel, cudaFuncAttributeMaxDynamicSharedMemorySize, smem_bytes);
        attr_set = true;
    }

    const int grid = (B + TBR - 1) / TBR;
    fused_kernel<<<grid, THREADS, smem_bytes>>>(nodes, neigh_idx, neigh_w, features, out, B);
}

// round 7
// speedup vs baseline: 1.2930x; 1.2930x over previous
#include <cuda_runtime.h>
#include <cuda_bf16.h>
#include <cstdint>
#include <math.h>

// ---------------------------------------------------------------------------
// Shapes fixed by the dataset
#define D_DIM   256
#define E_DIM   256
#define K_NEIGH 32
#define B_PAD   50048          // 391 * 128  (GEMM M-tile padded)

// Scratch (__device__ globals: no allocations allowed)
__device__ __nv_bfloat16 g_Xh[(size_t)B_PAD * 512];   // activation hi plane
__device__ __nv_bfloat16 g_Xl[(size_t)B_PAD * 512];   // activation lo plane
__device__ __nv_bfloat16 g_Wth[256 * 512];            // W^T hi  [e][k]
__device__ __nv_bfloat16 g_Wtl[256 * 512];            // W^T lo  [e][k]
__device__ float         g_bc[256];                   // fused bias

// ---------------------------------------------------------------------------
// Prep: fused weight Wz[512][256] -> transposed bf16 hi/lo planes + fused bias
//   rows 0..255 of Wz : W_init @ W_final[0:256]
//   rows 256..511     : W_final[256:512]
//   bc[e] = b_final[e] + sum_j b_init[j] * W_final[j][e]
// ---------------------------------------------------------------------------
static __device__ __forceinline__ void split_wt(float s, int e, int d) {
    __nv_bfloat16 h = __float2bfloat16_rn(s);
    float r = s - __bfloat162float(h);
    g_Wth[e * 512 + d] = h;
    g_Wtl[e * 512 + d] = __float2bfloat16_rn(r);
}

__global__ void __launch_bounds__(256) prep_kernel(const float* __restrict__ W_init,
                                                   const float* __restrict__ b_init,
                                                   const float* __restrict__ W_final,
                                                   const float* __restrict__ b_final) {
    __shared__ float sh[256];
    const int d = blockIdx.x;
    const int e = threadIdx.x;

    if (d < 256) {
        sh[e] = W_init[d * 256 + e];
        __syncthreads();
        float s = 0.f;
#pragma unroll 8
        for (int j = 0; j < 256; j++)
            s += sh[j] * W_final[j * 256 + e];
        split_wt(s, e, d);
    } else if (d < 512) {
        split_wt(W_final[d * 256 + e], e, d);
    } else {
        sh[e] = b_init[e];
        __syncthreads();
        float s = b_final[e];
#pragma unroll 8
        for (int j = 0; j < 256; j++)
            s += sh[j] * W_final[j * 256 + e];
        g_bc[e] = s;
    }
}

// ---------------------------------------------------------------------------
// Kernel 1: gather + weighted-mean aggregate -> X hi/lo bf16 planes
// 1 warp per output row, 8 rows per block, no smem -> max occupancy.
// ---------------------------------------------------------------------------
static __device__ __forceinline__ void split_store4(float4 v, __nv_bfloat16* hp, __nv_bfloat16* lp) {
    __nv_bfloat16 h0 = __float2bfloat16_rn(v.x), h1 = __float2bfloat16_rn(v.y),
                  h2 = __float2bfloat16_rn(v.z), h3 = __float2bfloat16_rn(v.w);
    float r0 = v.x - __bfloat162float(h0), r1 = v.y - __bfloat162float(h1),
          r2 = v.z - __bfloat162float(h2), r3 = v.w - __bfloat162float(h3);
    __nv_bfloat162 H0; H0.x = h0; H0.y = h1;
    __nv_bfloat162 H1; H1.x = h2; H1.y = h3;
    __nv_bfloat162 L0; L0.x = __float2bfloat16_rn(r0); L0.y = __float2bfloat16_rn(r1);
    __nv_bfloat162 L1; L1.x = __float2bfloat16_rn(r2); L1.y = __float2bfloat16_rn(r3);
    uint2 hu, lu;
    hu.x = *(uint32_t*)&H0; hu.y = *(uint32_t*)&H1;
    lu.x = *(uint32_t*)&L0; lu.y = *(uint32_t*)&L1;
    *(uint2*)hp = hu;
    *(uint2*)lp = lu;
}

__global__ void __launch_bounds__(256) gather_kernel(const int*   __restrict__ nodes,
                                                     const int*   __restrict__ neigh_idx,
                                                     const float* __restrict__ neigh_w,
                                                     const float* __restrict__ features,
                                                     int B) {
    const int wid  = threadIdx.x >> 5;
    const int lane = threadIdx.x & 31;
    const int b    = blockIdx.x * 8 + wid;
    if (b >= B_PAD) return;

    __nv_bfloat16* xh = g_Xh + (size_t)b * 512;
    __nv_bfloat16* xl = g_Xl + (size_t)b * 512;

    float4 s0, s1, a0, a1;
    if (b < B) {
        const int node = nodes[b];
        const float4* fs = (const float4*)(features + (size_t)node * D_DIM);
        s0 = fs[lane];
        s1 = fs[lane + 32];

        const float w_mine   = neigh_w[b * K_NEIGH + lane];
        const int   idx_mine = neigh_idx[b * K_NEIGH + lane];
        float ws = w_mine;
#pragma unroll
        for (int o = 16; o > 0; o >>= 1)
            ws += __shfl_xor_sync(0xffffffffu, ws, o);
        const float inv = 1.0f / ws;

        a0 = make_float4(0.f, 0.f, 0.f, 0.f);
        a1 = make_float4(0.f, 0.f, 0.f, 0.f);
#pragma unroll 4
        for (int k = 0; k < K_NEIGH; k++) {
            const float wk = __shfl_sync(0xffffffffu, w_mine, k) * inv;
            const int   ik = __shfl_sync(0xffffffffu, idx_mine, k);
            const float4* fn = (const float4*)(features + (size_t)ik * D_DIM);
            float4 v0 = fn[lane];
            float4 v1 = fn[lane + 32];
            a0.x += wk * v0.x; a0.y += wk * v0.y; a0.z += wk * v0.z; a0.w += wk * v0.w;
            a1.x += wk * v1.x; a1.y += wk * v1.y; a1.z += wk * v1.z; a1.w += wk * v1.w;
        }
    } else {
        s0 = s1 = a0 = a1 = make_float4(0.f, 0.f, 0.f, 0.f);
    }

    split_store4(s0, xh + lane * 4,       xl + lane * 4);
    split_store4(s1, xh + 128 + lane * 4, xl + 128 + lane * 4);
    split_store4(a0, xh + 256 + lane * 4, xl + 256 + lane * 4);
    split_store4(a1, xh + 384 + lane * 4, xl + 384 + lane * 4);
}

// ---------------------------------------------------------------------------
// Kernel 2: tensor-core GEMM via mma.sync (plain sm_80+ PTX, no 'a' features)
//   z = X[B_PAD x 512] * Wz[512 x 256], split bf16: D = Ah*Wh + Al*Wh + Ah*Wl
// CTA tile 128M x 128N, 8 warps (4M x 2N), warp tile 32x64, K chunk 64.
// smem rows padded to 72 elems -> conflict-free b32 fragment loads.
// ---------------------------------------------------------------------------
#define KC      64
#define KSTRIDE 72                 // padded row stride (bf16 elems)
#define PLANE   (128 * KSTRIDE)    // 9216 elems per plane

static __device__ __forceinline__ void mma16816(float* c, const uint32_t* a, const uint32_t* b) {
    asm volatile(
        "mma.sync.aligned.m16n8k16.row.col.f32.bf16.bf16.f32 "
        "{%0,%1,%2,%3}, {%4,%5,%6,%7}, {%8,%9}, {%0,%1,%2,%3};"
        : "+f"(c[0]), "+f"(c[1]), "+f"(c[2]), "+f"(c[3])
        : "r"(a[0]), "r"(a[1]), "r"(a[2]), "r"(a[3]), "r"(b[0]), "r"(b[1]));
}

__global__ void __launch_bounds__(256) gemm_kernel(float* __restrict__ out, int B) {
    extern __shared__ __nv_bfloat16 smem[];
    __nv_bfloat16* sAh = smem;
    __nv_bfloat16* sAl = smem + PLANE;
    __nv_bfloat16* sWh = smem + 2 * PLANE;
    __nv_bfloat16* sWl = smem + 3 * PLANE;

    const int tid  = threadIdx.x;
    const int wid  = tid >> 5;
    const int lane = tid & 31;
    const int b0   = (blockIdx.x >> 1) * 128;
    const int n0   = (blockIdx.x & 1) * 128;

    const int wm = (wid & 3) * 32;    // warp M offset in tile
    const int wn = (wid >> 2) * 64;   // warp N offset in tile

    const int qr = lane >> 2;         // 0..7 : fragment row group
    const int qc = lane & 3;          // 0..3 : fragment col pair

    float acc[2][8][4];
#pragma unroll
    for (int mi = 0; mi < 2; mi++)
#pragma unroll
        for (int ni = 0; ni < 8; ni++)
#pragma unroll
            for (int j = 0; j < 4; j++)
                acc[mi][ni][j] = 0.f;

    for (int chunk = 0; chunk < 8; chunk++) {
        const int kc = chunk * KC;
        __syncthreads();   // previous iteration's frags consumed

        // ---- cooperative stage: 128 rows x 64 elems per plane, uint4 (8 bf16) ----
#pragma unroll
        for (int it = 0; it < 4; it++) {
            const int i   = it * 256 + tid;
            const int row = i >> 3;
            const int seg = i & 7;
            const size_t goffA = (size_t)(b0 + row) * 512 + kc + seg * 8;
            const int    soff  = row * KSTRIDE + seg * 8;
            *(uint4*)(sAh + soff) = *(const uint4*)(g_Xh + goffA);
            *(uint4*)(sAl + soff) = *(const uint4*)(g_Xl + goffA);
            const size_t goffW = (size_t)(n0 + row) * 512 + kc + seg * 8;
            *(uint4*)(sWh + soff) = *(const uint4*)(g_Wth + goffW);
            *(uint4*)(sWl + soff) = *(const uint4*)(g_Wtl + goffW);
        }
        __syncthreads();

#pragma unroll
        for (int kk = 0; kk < KC; kk += 16) {
            // A fragments (hi & lo planes), 2 m-frags each
            uint32_t ah[2][4], al[2][4];
#pragma unroll
            for (int mi = 0; mi < 2; mi++) {
                const int r0 = wm + mi * 16 + qr;
                const int c0 = kk + qc * 2;
                ah[mi][0] = *(const uint32_t*)(sAh + (r0)     * KSTRIDE + c0);
                ah[mi][1] = *(const uint32_t*)(sAh + (r0 + 8) * KSTRIDE + c0);
                ah[mi][2] = *(const uint32_t*)(sAh + (r0)     * KSTRIDE + c0 + 8);
                ah[mi][3] = *(const uint32_t*)(sAh + (r0 + 8) * KSTRIDE + c0 + 8);
                al[mi][0] = *(const uint32_t*)(sAl + (r0)     * KSTRIDE + c0);
                al[mi][1] = *(const uint32_t*)(sAl + (r0 + 8) * KSTRIDE + c0);
                al[mi][2] = *(const uint32_t*)(sAl + (r0)     * KSTRIDE + c0 + 8);
                al[mi][3] = *(const uint32_t*)(sAl + (r0 + 8) * KSTRIDE + c0 + 8);
            }
#pragma unroll
            for (int ni = 0; ni < 8; ni++) {
                const int n  = wn + ni * 8 + qr;
                const int k0 = kk + qc * 2;
                uint32_t bh[2], bl[2];
                bh[0] = *(const uint32_t*)(sWh + n * KSTRIDE + k0);
                bh[1] = *(const uint32_t*)(sWh + n * KSTRIDE + k0 + 8);
                bl[0] = *(const uint32_t*)(sWl + n * KSTRIDE + k0);
                bl[1] = *(const uint32_t*)(sWl + n * KSTRIDE + k0 + 8);
#pragma unroll
                for (int mi = 0; mi < 2; mi++) {
                    mma16816(acc[mi][ni], ah[mi], bh);
                    mma16816(acc[mi][ni], al[mi], bh);
                    mma16816(acc[mi][ni], ah[mi], bl);
                }
            }
        }
    }

    // ---- epilogue: bias + swish + store ----
#pragma unroll
    for (int mi = 0; mi < 2; mi++) {
        const int row = b0 + wm + mi * 16 + qr;
#pragma unroll
        for (int ni = 0; ni < 8; ni++) {
            const int col = n0 + wn + ni * 8 + qc * 2;
            const float b_0 = g_bc[col], b_1 = g_bc[col + 1];

            if (row < B) {
                float z0 = acc[mi][ni][0] + b_0;
                float z1 = acc[mi][ni][1] + b_1;
                float2 o;
                o.x = z0 / (1.f + expf(-z0));
                o.y = z1 / (1.f + expf(-z1));
                *(float2*)(out + (size_t)row * E_DIM + col) = o;
            }
            if (row + 8 < B) {
                float z2 = acc[mi][ni][2] + b_0;
                float z3 = acc[mi][ni][3] + b_1;
                float2 o;
                o.x = z2 / (1.f + expf(-z2));
                o.y = z3 / (1.f + expf(-z3));
                *(float2*)(out + (size_t)(row + 8) * E_DIM + col) = o;
            }
        }
    }
}

// ---------------------------------------------------------------------------
extern "C" void kernel_launch(void* const* d_in, const int* in_sizes, int n_in,
                              void* d_out, int out_size) {
    const int*   nodes     = (const int*)  d_in[0];
    const int*   neigh_idx = (const int*)  d_in[1];
    const float* neigh_w   = (const float*)d_in[2];
    const float* features  = (const float*)d_in[3];
    const float* W_init    = (const float*)d_in[4];
    const float* b_init    = (const float*)d_in[5];
    const float* W_final   = (const float*)d_in[6];
    const float* b_final   = (const float*)d_in[7];
    float*       out       = (float*)d_out;

    const int B = in_sizes[0];

    const int smem_bytes = 4 * PLANE * (int)sizeof(__nv_bfloat16);  // 73728
    static bool attr_set = false;
    if (!attr_set) {
        cudaFuncSetAttribute(gemm_kernel, cudaFuncAttributeMaxDynamicSharedMemorySize, smem_bytes);
        attr_set = true;
    }

    prep_kernel<<<513, 256>>>(W_init, b_init, W_final, b_final);
    gather_kernel<<<B_PAD / 8, 256>>>(nodes, neigh_idx, neigh_w, features, B);
    gemm_kernel<<<(B_PAD / 128) * 2, 256, smem_bytes>>>(out, B);
}

// round 8
// speedup vs baseline: 1.4058x; 1.0873x over previous
#include <cuda_runtime.h>
#include <cuda_bf16.h>
#include <cuda_fp16.h>
#include <cstdint>
#include <math.h>

// ---------------------------------------------------------------------------
// Shapes fixed by the dataset
#define D_DIM   256
#define E_DIM   256
#define K_NEIGH 32
#define N_NODES 200000
#define B_PAD   50048          // 391 * 128  (GEMM M-tile padded)

// Scratch (__device__ globals: no allocations allowed)
__device__ __nv_bfloat16 g_Xh[(size_t)B_PAD * 512];   // activation hi plane
__device__ __nv_bfloat16 g_Xl[(size_t)B_PAD * 512];   // activation lo plane
__device__ __nv_bfloat16 g_Wth[256 * 512];            // W^T hi  [e][k]
__device__ __nv_bfloat16 g_Wtl[256 * 512];            // W^T lo  [e][k]
__device__ float         g_bc[256];                   // fused bias
__device__ __half        g_F16[(size_t)N_NODES * 256]; // fp16 feature table (neigh path)

// ---------------------------------------------------------------------------
// Convert kernel: features fp32 -> fp16 table (halves gather bytes; table
// becomes ~L2-resident at 102.4 MB)
// ---------------------------------------------------------------------------
__global__ void __launch_bounds__(256) convert_kernel(const float* __restrict__ features) {
    const size_t i = (size_t)blockIdx.x * 256 + threadIdx.x;   // one float4 each
    const size_t total = (size_t)N_NODES * 256 / 4;
    if (i >= total) return;
    float4 v = ((const float4*)features)[i];
    __half2 p0 = __floats2half2_rn(v.x, v.y);
    __half2 p1 = __floats2half2_rn(v.z, v.w);
    uint2 u;
    u.x = *(uint32_t*)&p0;
    u.y = *(uint32_t*)&p1;
    *(uint2*)(g_F16 + i * 4) = u;
}

// ---------------------------------------------------------------------------
// Prep: fused weight Wz[512][256] -> transposed bf16 hi/lo planes + fused bias
// ---------------------------------------------------------------------------
static __device__ __forceinline__ void split_wt(float s, int e, int d) {
    __nv_bfloat16 h = __float2bfloat16_rn(s);
    float r = s - __bfloat162float(h);
    g_Wth[e * 512 + d] = h;
    g_Wtl[e * 512 + d] = __float2bfloat16_rn(r);
}

__global__ void __launch_bounds__(256) prep_kernel(const float* __restrict__ W_init,
                                                   const float* __restrict__ b_init,
                                                   const float* __restrict__ W_final,
                                                   const float* __restrict__ b_final) {
    __shared__ float sh[256];
    const int d = blockIdx.x;
    const int e = threadIdx.x;

    if (d < 256) {
        sh[e] = W_init[d * 256 + e];
        __syncthreads();
        float s0 = 0.f, s1 = 0.f, s2 = 0.f, s3 = 0.f;
#pragma unroll 8
        for (int j = 0; j < 256; j += 4) {
            s0 += sh[j + 0] * W_final[(j + 0) * 256 + e];
            s1 += sh[j + 1] * W_final[(j + 1) * 256 + e];
            s2 += sh[j + 2] * W_final[(j + 2) * 256 + e];
            s3 += sh[j + 3] * W_final[(j + 3) * 256 + e];
        }
        split_wt((s0 + s1) + (s2 + s3), e, d);
    } else if (d < 512) {
        split_wt(W_final[d * 256 + e], e, d);
    } else {
        sh[e] = b_init[e];
        __syncthreads();
        float s0 = 0.f, s1 = 0.f, s2 = 0.f, s3 = 0.f;
#pragma unroll 8
        for (int j = 0; j < 256; j += 4) {
            s0 += sh[j + 0] * W_final[(j + 0) * 256 + e];
            s1 += sh[j + 1] * W_final[(j + 1) * 256 + e];
            s2 += sh[j + 2] * W_final[(j + 2) * 256 + e];
            s3 += sh[j + 3] * W_final[(j + 3) * 256 + e];
        }
        g_bc[e] = b_final[e] + (s0 + s1) + (s2 + s3);
    }
}

// ---------------------------------------------------------------------------
// Kernel 1: gather + weighted-mean aggregate -> X hi/lo bf16 planes
// Self path: exact fp32 feature row. Neighbor path: fp16 table (half bytes).
// 1 warp per output row, 8 rows per block, no smem -> max occupancy.
// ---------------------------------------------------------------------------
static __device__ __forceinline__ void split_store4(float4 v, __nv_bfloat16* hp, __nv_bfloat16* lp) {
    __nv_bfloat16 h0 = __float2bfloat16_rn(v.x), h1 = __float2bfloat16_rn(v.y),
                  h2 = __float2bfloat16_rn(v.z), h3 = __float2bfloat16_rn(v.w);
    float r0 = v.x - __bfloat162float(h0), r1 = v.y - __bfloat162float(h1),
          r2 = v.z - __bfloat162float(h2), r3 = v.w - __bfloat162float(h3);
    __nv_bfloat162 H0; H0.x = h0; H0.y = h1;
    __nv_bfloat162 H1; H1.x = h2; H1.y = h3;
    __nv_bfloat162 L0; L0.x = __float2bfloat16_rn(r0); L0.y = __float2bfloat16_rn(r1);
    __nv_bfloat162 L1; L1.x = __float2bfloat16_rn(r2); L1.y = __float2bfloat16_rn(r3);
    uint2 hu, lu;
    hu.x = *(uint32_t*)&H0; hu.y = *(uint32_t*)&H1;
    lu.x = *(uint32_t*)&L0; lu.y = *(uint32_t*)&L1;
    *(uint2*)hp = hu;
    *(uint2*)lp = lu;
}

__global__ void __launch_bounds__(256) gather_kernel(const int*   __restrict__ nodes,
                                                     const int*   __restrict__ neigh_idx,
                                                     const float* __restrict__ neigh_w,
                                                     const float* __restrict__ features,
                                                     int B) {
    const int wid  = threadIdx.x >> 5;
    const int lane = threadIdx.x & 31;
    const int b    = blockIdx.x * 8 + wid;
    if (b >= B_PAD) return;

    __nv_bfloat16* xh = g_Xh + (size_t)b * 512;
    __nv_bfloat16* xl = g_Xl + (size_t)b * 512;

    float4 s0, s1, a0, a1;
    if (b < B) {
        // self: exact fp32 row
        const int node = nodes[b];
        const float4* fs = (const float4*)(features + (size_t)node * D_DIM);
        s0 = fs[lane];
        s1 = fs[lane + 32];

        const float w_mine   = neigh_w[b * K_NEIGH + lane];
        const int   idx_mine = neigh_idx[b * K_NEIGH + lane];
        float ws = w_mine;
#pragma unroll
        for (int o = 16; o > 0; o >>= 1)
            ws += __shfl_xor_sync(0xffffffffu, ws, o);
        const float inv = 1.0f / ws;

        a0 = make_float4(0.f, 0.f, 0.f, 0.f);
        a1 = make_float4(0.f, 0.f, 0.f, 0.f);
#pragma unroll 4
        for (int k = 0; k < K_NEIGH; k++) {
            const float wk = __shfl_sync(0xffffffffu, w_mine, k) * inv;
            const int   ik = __shfl_sync(0xffffffffu, idx_mine, k);
            // 8 contiguous fp16 elements per lane: one 16B load
            uint4 v = *(const uint4*)(g_F16 + (size_t)ik * 256 + lane * 8);
            float2 f0 = __half22float2(*(__half2*)&v.x);
            float2 f1 = __half22float2(*(__half2*)&v.y);
            float2 f2 = __half22float2(*(__half2*)&v.z);
            float2 f3 = __half22float2(*(__half2*)&v.w);
            a0.x += wk * f0.x; a0.y += wk * f0.y; a0.z += wk * f1.x; a0.w += wk * f1.y;
            a1.x += wk * f2.x; a1.y += wk * f2.y; a1.z += wk * f3.x; a1.w += wk * f3.y;
        }
    } else {
        s0 = s1 = a0 = a1 = make_float4(0.f, 0.f, 0.f, 0.f);
    }

    // self features occupy cols [0,256): lanes interleave float4 slots 0..63
    split_store4(s0, xh + lane * 4,       xl + lane * 4);
    split_store4(s1, xh + 128 + lane * 4, xl + 128 + lane * 4);
    // neighbor aggregate cols [256,512): lane holds elems lane*8..lane*8+7
    split_store4(a0, xh + 256 + lane * 8,     xl + 256 + lane * 8);
    split_store4(a1, xh + 256 + lane * 8 + 4, xl + 256 + lane * 8 + 4);
}

// ---------------------------------------------------------------------------
// Kernel 2: tensor-core GEMM via mma.sync (plain sm_80+ PTX, no 'a' features)
//   z = X[B_PAD x 512] * Wz[512 x 256], split bf16: D = Ah*Wh + Al*Wh + Ah*Wl
// CTA tile 128M x 128N, 8 warps (4M x 2N), warp tile 32x64, K chunk 64.
// NOTE: neighbor half of X is stored with lane*8 layout; K (columns of X) is
// still plain contiguous order — layout identical to R7 (lane*8 covers the
// same contiguous 8 elems the two float4 stores covered). GEMM unchanged.
// ---------------------------------------------------------------------------
#define KC      64
#define KSTRIDE 72                 // padded row stride (bf16 elems)
#define PLANE   (128 * KSTRIDE)    // 9216 elems per plane

static __device__ __forceinline__ void mma16816(float* c, const uint32_t* a, const uint32_t* b) {
    asm volatile(
        "mma.sync.aligned.m16n8k16.row.col.f32.bf16.bf16.f32 "
        "{%0,%1,%2,%3}, {%4,%5,%6,%7}, {%8,%9}, {%0,%1,%2,%3};"
        : "+f"(c[0]), "+f"(c[1]), "+f"(c[2]), "+f"(c[3])
        : "r"(a[0]), "r"(a[1]), "r"(a[2]), "r"(a[3]), "r"(b[0]), "r"(b[1]));
}

__global__ void __launch_bounds__(256) gemm_kernel(float* __restrict__ out, int B) {
    extern __shared__ __nv_bfloat16 smem[];
    __nv_bfloat16* sAh = smem;
    __nv_bfloat16* sAl = smem + PLANE;
    __nv_bfloat16* sWh = smem + 2 * PLANE;
    __nv_bfloat16* sWl = smem + 3 * PLANE;

    const int tid  = threadIdx.x;
    const int wid  = tid >> 5;
    const int lane = tid & 31;
    const int b0   = (blockIdx.x >> 1) * 128;
    const int n0   = (blockIdx.x & 1) * 128;

    const int wm = (wid & 3) * 32;    // warp M offset in tile
    const int wn = (wid >> 2) * 64;   // warp N offset in tile

    const int qr = lane >> 2;         // 0..7 : fragment row group
    const int qc = lane & 3;          // 0..3 : fragment col pair

    float acc[2][8][4];
#pragma unroll
    for (int mi = 0; mi < 2; mi++)
#pragma unroll
        for (int ni = 0; ni < 8; ni++)
#pragma unroll
            for (int j = 0; j < 4; j++)
                acc[mi][ni][j] = 0.f;

    for (int chunk = 0; chunk < 8; chunk++) {
        const int kc = chunk * KC;
        __syncthreads();   // previous iteration's frags consumed

        // ---- cooperative stage: 128 rows x 64 elems per plane, uint4 (8 bf16) ----
#pragma unroll
        for (int it = 0; it < 4; it++) {
            const int i   = it * 256 + tid;
            const int row = i >> 3;
            const int seg = i & 7;
            const size_t goffA = (size_t)(b0 + row) * 512 + kc + seg * 8;
            const int    soff  = row * KSTRIDE + seg * 8;
            *(uint4*)(sAh + soff) = *(const uint4*)(g_Xh + goffA);
            *(uint4*)(sAl + soff) = *(const uint4*)(g_Xl + goffA);
            const size_t goffW = (size_t)(n0 + row) * 512 + kc + seg * 8;
            *(uint4*)(sWh + soff) = *(const uint4*)(g_Wth + goffW);
            *(uint4*)(sWl + soff) = *(const uint4*)(g_Wtl + goffW);
        }
        __syncthreads();

#pragma unroll
        for (int kk = 0; kk < KC; kk += 16) {
            uint32_t ah[2][4], al[2][4];
#pragma unroll
            for (int mi = 0; mi < 2; mi++) {
                const int r0 = wm + mi * 16 + qr;
                const int c0 = kk + qc * 2;
                ah[mi][0] = *(const uint32_t*)(sAh + (r0)     * KSTRIDE + c0);
                ah[mi][1] = *(const uint32_t*)(sAh + (r0 + 8) * KSTRIDE + c0);
                ah[mi][2] = *(const uint32_t*)(sAh + (r0)     * KSTRIDE + c0 + 8);
                ah[mi][3] = *(const uint32_t*)(sAh + (r0 + 8) * KSTRIDE + c0 + 8);
                al[mi][0] = *(const uint32_t*)(sAl + (r0)     * KSTRIDE + c0);
                al[mi][1] = *(const uint32_t*)(sAl + (r0 + 8) * KSTRIDE + c0);
                al[mi][2] = *(const uint32_t*)(sAl + (r0)     * KSTRIDE + c0 + 8);
                al[mi][3] = *(const uint32_t*)(sAl + (r0 + 8) * KSTRIDE + c0 + 8);
            }
#pragma unroll
            for (int ni = 0; ni < 8; ni++) {
                const int n  = wn + ni * 8 + qr;
                const int k0 = kk + qc * 2;
                uint32_t bh[2], bl[2];
                bh[0] = *(const uint32_t*)(sWh + n * KSTRIDE + k0);
                bh[1] = *(const uint32_t*)(sWh + n * KSTRIDE + k0 + 8);
                bl[0] = *(const uint32_t*)(sWl + n * KSTRIDE + k0);
                bl[1] = *(const uint32_t*)(sWl + n * KSTRIDE + k0 + 8);
#pragma unroll
                for (int mi = 0; mi < 2; mi++) {
                    mma16816(acc[mi][ni], ah[mi], bh);
                    mma16816(acc[mi][ni], al[mi], bh);
                    mma16816(acc[mi][ni], ah[mi], bl);
                }
            }
        }
    }

    // ---- epilogue: bias + swish + store ----
#pragma unroll
    for (int mi = 0; mi < 2; mi++) {
        const int row = b0 + wm + mi * 16 + qr;
#pragma unroll
        for (int ni = 0; ni < 8; ni++) {
            const int col = n0 + wn + ni * 8 + qc * 2;
            const float b_0 = g_bc[col], b_1 = g_bc[col + 1];

            if (row < B) {
                float z0 = acc[mi][ni][0] + b_0;
                float z1 = acc[mi][ni][1] + b_1;
                float2 o;
                o.x = z0 / (1.f + expf(-z0));
                o.y = z1 / (1.f + expf(-z1));
                *(float2*)(out + (size_t)row * E_DIM + col) = o;
            }
            if (row + 8 < B) {
                float z2 = acc[mi][ni][2] + b_0;
                float z3 = acc[mi][ni][3] + b_1;
                float2 o;
                o.x = z2 / (1.f + expf(-z2));
                o.y = z3 / (1.f + expf(-z3));
                *(float2*)(out + (size_t)(row + 8) * E_DIM + col) = o;
            }
        }
    }
}

// ---------------------------------------------------------------------------
extern "C" void kernel_launch(void* const* d_in, const int* in_sizes, int n_in,
                              void* d_out, int out_size) {
    const int*   nodes     = (const int*)  d_in[0];
    const int*   neigh_idx = (const int*)  d_in[1];
    const float* neigh_w   = (const float*)d_in[2];
    const float* features  = (const float*)d_in[3];
    const float* W_init    = (const float*)d_in[4];
    const float* b_init    = (const float*)d_in[5];
    const float* W_final   = (const float*)d_in[6];
    const float* b_final   = (const float*)d_in[7];
    float*       out       = (float*)d_out;

    const int B = in_sizes[0];

    const int smem_bytes = 4 * PLANE * (int)sizeof(__nv_bfloat16);  // 73728
    static bool attr_set = false;
    if (!attr_set) {
        cudaFuncSetAttribute(gemm_kernel, cudaFuncAttributeMaxDynamicSharedMemorySize, smem_bytes);
        attr_set = true;
    }

    const int conv_blocks = (int)(((size_t)N_NODES * 256 / 4 + 255) / 256);
    convert_kernel<<<conv_blocks, 256>>>(features);
    prep_kernel<<<513, 256>>>(W_init, b_init, W_final, b_final);
    gather_kernel<<<B_PAD / 8, 256>>>(nodes, neigh_idx, neigh_w, features, B);
    gemm_kernel<<<(B_PAD / 128) * 2, 256, smem_bytes>>>(out, B);
}

// round 9
// speedup vs baseline: 1.7973x; 1.2785x over previous
#include <cuda_runtime.h>
#include <cuda_bf16.h>
#include <cuda_fp16.h>
#include <cstdint>
#include <math.h>

// ---------------------------------------------------------------------------
// Shapes fixed by the dataset
#define D_DIM   256
#define E_DIM   256
#define K_NEIGH 32
#define N_NODES 200000
#define B_PAD   50048          // 391 * 128  (GEMM M-tile padded)

// Scratch (__device__ globals: no allocations allowed)
__device__ __nv_bfloat16 g_Xh[(size_t)B_PAD * 512];   // activation hi plane
__device__ __nv_bfloat16 g_Xl[(size_t)B_PAD * 512];   // activation lo plane
__device__ __nv_bfloat16 g_Wth[256 * 512];            // W^T hi  [e][k]
__device__ __nv_bfloat16 g_Wtl[256 * 512];            // W^T lo  [e][k]
__device__ float         g_bc[256];                   // fused bias
__device__ __half        g_F16[(size_t)N_NODES * 256]; // fp16 feature table (neigh path)

// ---------------------------------------------------------------------------
// Setup kernel: merged feature fp32->fp16 convert + fused-weight prep.
// blocks [0, 50000)           : convert (one float4 per thread)
// blocks [50000, 50513)       : prep (d = blockIdx - 50000)
// ---------------------------------------------------------------------------
#define CONV_BLOCKS 50000      // 200000*256/4 / 256

static __device__ __forceinline__ void split_wt(float s, int e, int d) {
    __nv_bfloat16 h = __float2bfloat16_rn(s);
    float r = s - __bfloat162float(h);
    g_Wth[e * 512 + d] = h;
    g_Wtl[e * 512 + d] = __float2bfloat16_rn(r);
}

__global__ void __launch_bounds__(256) setup_kernel(const float* __restrict__ features,
                                                    const float* __restrict__ W_init,
                                                    const float* __restrict__ b_init,
                                                    const float* __restrict__ W_final,
                                                    const float* __restrict__ b_final) {
    if (blockIdx.x < CONV_BLOCKS) {
        const size_t i = (size_t)blockIdx.x * 256 + threadIdx.x;   // one float4 each
        float4 v = ((const float4*)features)[i];
        __half2 p0 = __floats2half2_rn(v.x, v.y);
        __half2 p1 = __floats2half2_rn(v.z, v.w);
        uint2 u;
        u.x = *(uint32_t*)&p0;
        u.y = *(uint32_t*)&p1;
        *(uint2*)(g_F16 + i * 4) = u;
        return;
    }

    __shared__ float sh[256];
    const int d = blockIdx.x - CONV_BLOCKS;
    const int e = threadIdx.x;

    if (d < 256) {
        sh[e] = W_init[d * 256 + e];
        __syncthreads();
        float s0 = 0.f, s1 = 0.f, s2 = 0.f, s3 = 0.f;
#pragma unroll 8
        for (int j = 0; j < 256; j += 4) {
            s0 += sh[j + 0] * W_final[(j + 0) * 256 + e];
            s1 += sh[j + 1] * W_final[(j + 1) * 256 + e];
            s2 += sh[j + 2] * W_final[(j + 2) * 256 + e];
            s3 += sh[j + 3] * W_final[(j + 3) * 256 + e];
        }
        split_wt((s0 + s1) + (s2 + s3), e, d);
    } else if (d < 512) {
        split_wt(W_final[d * 256 + e], e, d);
    } else {
        sh[e] = b_init[e];
        __syncthreads();
        float s0 = 0.f, s1 = 0.f, s2 = 0.f, s3 = 0.f;
#pragma unroll 8
        for (int j = 0; j < 256; j += 4) {
            s0 += sh[j + 0] * W_final[(j + 0) * 256 + e];
            s1 += sh[j + 1] * W_final[(j + 1) * 256 + e];
            s2 += sh[j + 2] * W_final[(j + 2) * 256 + e];
            s3 += sh[j + 3] * W_final[(j + 3) * 256 + e];
        }
        g_bc[e] = b_final[e] + (s0 + s1) + (s2 + s3);
    }
}

// ---------------------------------------------------------------------------
// Kernel 1: gather + weighted-mean aggregate -> X hi/lo bf16 planes
// Self path: exact fp32 feature row. Neighbor path: fp16 table (half bytes).
// ---------------------------------------------------------------------------
static __device__ __forceinline__ void split_store4(float4 v, __nv_bfloat16* hp, __nv_bfloat16* lp) {
    __nv_bfloat16 h0 = __float2bfloat16_rn(v.x), h1 = __float2bfloat16_rn(v.y),
                  h2 = __float2bfloat16_rn(v.z), h3 = __float2bfloat16_rn(v.w);
    float r0 = v.x - __bfloat162float(h0), r1 = v.y - __bfloat162float(h1),
          r2 = v.z - __bfloat162float(h2), r3 = v.w - __bfloat162float(h3);
    __nv_bfloat162 H0; H0.x = h0; H0.y = h1;
    __nv_bfloat162 H1; H1.x = h2; H1.y = h3;
    __nv_bfloat162 L0; L0.x = __float2bfloat16_rn(r0); L0.y = __float2bfloat16_rn(r1);
    __nv_bfloat162 L1; L1.x = __float2bfloat16_rn(r2); L1.y = __float2bfloat16_rn(r3);
    uint2 hu, lu;
    hu.x = *(uint32_t*)&H0; hu.y = *(uint32_t*)&H1;
    lu.x = *(uint32_t*)&L0; lu.y = *(uint32_t*)&L1;
    *(uint2*)hp = hu;
    *(uint2*)lp = lu;
}

__global__ void __launch_bounds__(256) gather_kernel(const int*   __restrict__ nodes,
                                                     const int*   __restrict__ neigh_idx,
                                                     const float* __restrict__ neigh_w,
                                                     const float* __restrict__ features,
                                                     int B) {
    const int wid  = threadIdx.x >> 5;
    const int lane = threadIdx.x & 31;
    const int b    = blockIdx.x * 8 + wid;
    if (b >= B_PAD) return;

    __nv_bfloat16* xh = g_Xh + (size_t)b * 512;
    __nv_bfloat16* xl = g_Xl + (size_t)b * 512;

    float4 s0, s1, a0, a1;
    if (b < B) {
        const int node = nodes[b];
        const float4* fs = (const float4*)(features + (size_t)node * D_DIM);
        s0 = fs[lane];
        s1 = fs[lane + 32];

        const float w_mine   = neigh_w[b * K_NEIGH + lane];
        const int   idx_mine = neigh_idx[b * K_NEIGH + lane];
        float ws = w_mine;
#pragma unroll
        for (int o = 16; o > 0; o >>= 1)
            ws += __shfl_xor_sync(0xffffffffu, ws, o);
        const float inv = 1.0f / ws;

        a0 = make_float4(0.f, 0.f, 0.f, 0.f);
        a1 = make_float4(0.f, 0.f, 0.f, 0.f);
#pragma unroll 4
        for (int k = 0; k < K_NEIGH; k++) {
            const float wk = __shfl_sync(0xffffffffu, w_mine, k) * inv;
            const int   ik = __shfl_sync(0xffffffffu, idx_mine, k);
            uint4 v = *(const uint4*)(g_F16 + (size_t)ik * 256 + lane * 8);
            float2 f0 = __half22float2(*(__half2*)&v.x);
            float2 f1 = __half22float2(*(__half2*)&v.y);
            float2 f2 = __half22float2(*(__half2*)&v.z);
            float2 f3 = __half22float2(*(__half2*)&v.w);
            a0.x += wk * f0.x; a0.y += wk * f0.y; a0.z += wk * f1.x; a0.w += wk * f1.y;
            a1.x += wk * f2.x; a1.y += wk * f2.y; a1.z += wk * f3.x; a1.w += wk * f3.y;
        }
    } else {
        s0 = s1 = a0 = a1 = make_float4(0.f, 0.f, 0.f, 0.f);
    }

    split_store4(s0, xh + lane * 4,       xl + lane * 4);
    split_store4(s1, xh + 128 + lane * 4, xl + 128 + lane * 4);
    split_store4(a0, xh + 256 + lane * 8,     xl + 256 + lane * 8);
    split_store4(a1, xh + 256 + lane * 8 + 4, xl + 256 + lane * 8 + 4);
}

// ---------------------------------------------------------------------------
// Kernel 2: tensor-core GEMM via mma.sync, cp.async double-buffered.
//   z = X[B_PAD x 512] * Wz[512 x 256], split bf16: D = Ah*Wh + Al*Wh + Ah*Wl
// CTA tile 128M x 128N, 8 warps (4M x 2N), warp tile 32x64.
// KC=32 per stage, 16 stages, 2 smem buffers (40KB each), 2 CTAs/SM.
// ---------------------------------------------------------------------------
#define KC       32
#define KSTRIDE  40                  // padded row stride (bf16 elems) — conflict-free
#define PLANE_E  (128 * KSTRIDE)     // 5120 elems per plane
#define STAGE_E  (4 * PLANE_E)       // 20480 elems per stage
#define STAGE_B  (STAGE_E * 2)       // 40960 bytes
#define SMEM_B   (2 * STAGE_B)       // 81920 bytes

static __device__ __forceinline__ uint32_t smem_u32(const void* p) {
    uint32_t a;
    asm("{ .reg .u64 t; cvta.to.shared.u64 t, %1; cvt.u32.u64 %0, t; }" : "=r"(a) : "l"(p));
    return a;
}
static __device__ __forceinline__ void cp16(uint32_t saddr, const void* g) {
    asm volatile("cp.async.cg.shared.global [%0], [%1], 16;"
                 :: "r"(saddr), "l"((size_t)__cvta_generic_to_global(g)));
}
#define CP_COMMIT() asm volatile("cp.async.commit_group;" ::: "memory")
#define CP_WAIT(n)  asm volatile("cp.async.wait_group %0;" :: "n"(n) : "memory")

static __device__ __forceinline__ void mma16816(float* c, const uint32_t* a, const uint32_t* b) {
    asm volatile(
        "mma.sync.aligned.m16n8k16.row.col.f32.bf16.bf16.f32 "
        "{%0,%1,%2,%3}, {%4,%5,%6,%7}, {%8,%9}, {%0,%1,%2,%3};"
        : "+f"(c[0]), "+f"(c[1]), "+f"(c[2]), "+f"(c[3])
        : "r"(a[0]), "r"(a[1]), "r"(a[2]), "r"(a[3]), "r"(b[0]), "r"(b[1]));
}

__global__ void __launch_bounds__(256, 2) gemm_kernel(float* __restrict__ out, int B) {
    extern __shared__ __nv_bfloat16 smem[];
    const uint32_t sbase = smem_u32(smem);

    const int tid  = threadIdx.x;
    const int wid  = tid >> 5;
    const int lane = tid & 31;
    const int b0   = (blockIdx.x >> 1) * 128;
    const int n0   = (blockIdx.x & 1) * 128;

    const int wm = (wid & 3) * 32;    // warp M offset
    const int wn = (wid >> 2) * 64;   // warp N offset
    const int qr = lane >> 2;         // 0..7
    const int qc = lane & 3;          // 0..3

    // staging indices for this thread (2 x 16B per plane per stage)
    const int i0   = tid;             // 0..255
    const int i1   = tid + 256;       // 256..511
    const int row0 = i0 >> 2, seg0 = i0 & 3;
    const int row1 = i1 >> 2, seg1 = i1 & 3;

    float acc[2][8][4];
#pragma unroll
    for (int mi = 0; mi < 2; mi++)
#pragma unroll
        for (int ni = 0; ni < 8; ni++)
#pragma unroll
            for (int j = 0; j < 4; j++)
                acc[mi][ni][j] = 0.f;

    // ---- prefetch helper (macro-ish lambda) ----
    auto prefetch = [&](int buf, int kc) {
        const uint32_t sb = sbase + (uint32_t)buf * STAGE_B;
        {
            const size_t goA = (size_t)(b0 + row0) * 512 + kc + seg0 * 8;
            const size_t goW = (size_t)(n0 + row0) * 512 + kc + seg0 * 8;
            const uint32_t so = (uint32_t)(row0 * KSTRIDE + seg0 * 8) * 2;
            cp16(sb + so,                  g_Xh  + goA);
            cp16(sb + PLANE_E * 2 + so,    g_Xl  + goA);
            cp16(sb + PLANE_E * 4 + so,    g_Wth + goW);
            cp16(sb + PLANE_E * 6 + so,    g_Wtl + goW);
        }
        {
            const size_t goA = (size_t)(b0 + row1) * 512 + kc + seg1 * 8;
            const size_t goW = (size_t)(n0 + row1) * 512 + kc + seg1 * 8;
            const uint32_t so = (uint32_t)(row1 * KSTRIDE + seg1 * 8) * 2;
            cp16(sb + so,                  g_Xh  + goA);
            cp16(sb + PLANE_E * 2 + so,    g_Xl  + goA);
            cp16(sb + PLANE_E * 4 + so,    g_Wth + goW);
            cp16(sb + PLANE_E * 6 + so,    g_Wtl + goW);
        }
    };

    prefetch(0, 0);
    CP_COMMIT();

    for (int chunk = 0; chunk < 16; chunk++) {
        if (chunk + 1 < 16) {
            prefetch((chunk + 1) & 1, (chunk + 1) * KC);
            CP_COMMIT();
            CP_WAIT(1);          // current buffer's loads complete
        } else {
            CP_WAIT(0);
        }
        __syncthreads();

        const __nv_bfloat16* st  = smem + (chunk & 1) * STAGE_E;
        const __nv_bfloat16* sAh = st;
        const __nv_bfloat16* sAl = st + PLANE_E;
        const __nv_bfloat16* sWh = st + 2 * PLANE_E;
        const __nv_bfloat16* sWl = st + 3 * PLANE_E;

#pragma unroll
        for (int kk = 0; kk < KC; kk += 16) {
            uint32_t ah[2][4], al[2][4];
#pragma unroll
            for (int mi = 0; mi < 2; mi++) {
                const int r0 = wm + mi * 16 + qr;
                const int c0 = kk + qc * 2;
                ah[mi][0] = *(const uint32_t*)(sAh + (r0)     * KSTRIDE + c0);
                ah[mi][1] = *(const uint32_t*)(sAh + (r0 + 8) * KSTRIDE + c0);
                ah[mi][2] = *(const uint32_t*)(sAh + (r0)     * KSTRIDE + c0 + 8);
                ah[mi][3] = *(const uint32_t*)(sAh + (r0 + 8) * KSTRIDE + c0 + 8);
                al[mi][0] = *(const uint32_t*)(sAl + (r0)     * KSTRIDE + c0);
                al[mi][1] = *(const uint32_t*)(sAl + (r0 + 8) * KSTRIDE + c0);
                al[mi][2] = *(const uint32_t*)(sAl + (r0)     * KSTRIDE + c0 + 8);
                al[mi][3] = *(const uint32_t*)(sAl + (r0 + 8) * KSTRIDE + c0 + 8);
            }
#pragma unroll
            for (int ni = 0; ni < 8; ni++) {
                const int n  = wn + ni * 8 + qr;
                const int k0 = kk + qc * 2;
                uint32_t bh[2], bl[2];
                bh[0] = *(const uint32_t*)(sWh + n * KSTRIDE + k0);
                bh[1] = *(const uint32_t*)(sWh + n * KSTRIDE + k0 + 8);
                bl[0] = *(const uint32_t*)(sWl + n * KSTRIDE + k0);
                bl[1] = *(const uint32_t*)(sWl + n * KSTRIDE + k0 + 8);
#pragma unroll
                for (int mi = 0; mi < 2; mi++) {
                    mma16816(acc[mi][ni], ah[mi], bh);
                    mma16816(acc[mi][ni], al[mi], bh);
                    mma16816(acc[mi][ni], ah[mi], bl);
                }
            }
        }
        __syncthreads();   // buffer consumed; next iteration may overwrite it
    }

    // ---- epilogue: bias + swish + store ----
#pragma unroll
    for (int mi = 0; mi < 2; mi++) {
        const int row = b0 + wm + mi * 16 + qr;
#pragma unroll
        for (int ni = 0; ni < 8; ni++) {
            const int col = n0 + wn + ni * 8 + qc * 2;
            const float b_0 = g_bc[col], b_1 = g_bc[col + 1];

            if (row < B) {
                float z0 = acc[mi][ni][0] + b_0;
                float z1 = acc[mi][ni][1] + b_1;
                float2 o;
                o.x = z0 / (1.f + expf(-z0));
                o.y = z1 / (1.f + expf(-z1));
                *(float2*)(out + (size_t)row * E_DIM + col) = o;
            }
            if (row + 8 < B) {
                float z2 = acc[mi][ni][2] + b_0;
                float z3 = acc[mi][ni][3] + b_1;
                float2 o;
                o.x = z2 / (1.f + expf(-z2));
                o.y = z3 / (1.f + expf(-z3));
                *(float2*)(out + (size_t)(row + 8) * E_DIM + col) = o;
            }
        }
    }
}

// ---------------------------------------------------------------------------
extern "C" void kernel_launch(void* const* d_in, const int* in_sizes, int n_in,
                              void* d_out, int out_size) {
    const int*   nodes     = (const int*)  d_in[0];
    const int*   neigh_idx = (const int*)  d_in[1];
    const float* neigh_w   = (const float*)d_in[2];
    const float* features  = (const float*)d_in[3];
    const float* W_init    = (const float*)d_in[4];
    const float* b_init    = (const float*)d_in[5];
    const float* W_final   = (const float*)d_in[6];
    const float* b_final   = (const float*)d_in[7];
    float*       out       = (float*)d_out;

    const int B = in_sizes[0];

    static bool attr_set = false;
    if (!attr_set) {
        cudaFuncSetAttribute(gemm_kernel, cudaFuncAttributeMaxDynamicSharedMemorySize, SMEM_B);
        attr_set = true;
    }

    setup_kernel<<<CONV_BLOCKS + 513, 256>>>(features, W_init, b_init, W_final, b_final);
    gather_kernel<<<B_PAD / 8, 256>>>(nodes, neigh_idx, neigh_w, features, B);
    gemm_kernel<<<(B_PAD / 128) * 2, 256, SMEM_B>>>(out, B);
}